// round 2
// baseline (speedup 1.0000x reference)
#include <cuda_runtime.h>
#include <cuda_bf16.h>

// Problem: x[1,512,64,64] fp32, W_qkv[512,1536], b_qkv[1536]
// N = 4096 tokens, E = 512, H = 8 heads, dh = 64, scale = 0.125
//
// qkv[n, j] = sum_e x[e*4096+n] * W[e*1536+j] + b[j]
// q = qkv[:, 0:512], k = qkv[:, 512:1024], v = qkv[:, 1024:1536]
// M_h = K_h^T V_h (64x64), qsum_h = sum_n q_h[n]
// output[h,n,d]  = scale * sum_d1 q_h[n,d1] * M_h[d1,d]
// coarse[h,n]    = scale * dot(qsum_h, k_h[n])
// d_out layout: [coarse (8*4096)] then [output (8*4096*64)]

#define NTOK   4096
#define E3     1536
#define NCHUNK 32          // n-chunks for deterministic head reduction
#define CHUNK  (NTOK / NCHUNK)

__device__ float g_qkv[NTOK * E3];                       // 24 MB scratch
__device__ float g_Mpart[NCHUNK * 8 * 64 * 64];          // 4 MB partials
__device__ float g_qsumpart[NCHUNK * 512];
__device__ float g_M[8 * 64 * 64];
__device__ float g_qsum[512];

// ---------------------------------------------------------------------------
// Kernel 1: QKV GEMM  C[4096,1536] = X^T[4096,512] @ W[512,1536] + b
// 128x128 tile, BK=8, 256 threads, 8x8 per-thread register block.
// Both operands are K-major => fully coalesced float4 loads, no smem transpose.
// ---------------------------------------------------------------------------
__global__ __launch_bounds__(256, 2)
void qkv_gemm_kernel(const float* __restrict__ X,
                     const float* __restrict__ W,
                     const float* __restrict__ bias)
{
    __shared__ float As[8][128];
    __shared__ float Bs[8][128];

    const int bm = blockIdx.y * 128;   // token rows
    const int bn = blockIdx.x * 128;   // qkv cols
    const int tid = threadIdx.x;

    const int arow = tid >> 5;          // 0..7
    const int acol = (tid & 31) << 2;   // 0..124

    const int tm = (tid >> 4) << 3;     // 0..120
    const int tn = (tid & 15) << 3;     // 0..120

    float acc[8][8];
#pragma unroll
    for (int i = 0; i < 8; i++)
#pragma unroll
        for (int j = 0; j < 8; j++) acc[i][j] = 0.0f;

    float4 av = *(const float4*)&X[(arow) * NTOK + bm + acol];
    float4 bv = *(const float4*)&W[(arow) * E3 + bn + acol];

    for (int k0 = 0; k0 < 512; k0 += 8) {
        *(float4*)&As[arow][acol] = av;
        *(float4*)&Bs[arow][acol] = bv;
        __syncthreads();

        if (k0 + 8 < 512) {
            av = *(const float4*)&X[(k0 + 8 + arow) * NTOK + bm + acol];
            bv = *(const float4*)&W[(k0 + 8 + arow) * E3 + bn + acol];
        }

#pragma unroll
        for (int kk = 0; kk < 8; kk++) {
            float a[8], b[8];
#pragma unroll
            for (int i = 0; i < 8; i++) a[i] = As[kk][tm + i];
#pragma unroll
            for (int j = 0; j < 8; j++) b[j] = Bs[kk][tn + j];
#pragma unroll
            for (int i = 0; i < 8; i++)
#pragma unroll
                for (int j = 0; j < 8; j++)
                    acc[i][j] = fmaf(a[i], b[j], acc[i][j]);
        }
        __syncthreads();
    }

    // epilogue: add bias, store
#pragma unroll
    for (int i = 0; i < 8; i++) {
        const int row = bm + tm + i;
#pragma unroll
        for (int j = 0; j < 8; j += 4) {
            const int col = bn + tn + j;
            float4 o;
            o.x = acc[i][j + 0] + bias[col + 0];
            o.y = acc[i][j + 1] + bias[col + 1];
            o.z = acc[i][j + 2] + bias[col + 2];
            o.w = acc[i][j + 3] + bias[col + 3];
            *(float4*)&g_qkv[row * E3 + col] = o;
        }
    }
}

// ---------------------------------------------------------------------------
// Kernel 2: per-head partial reductions over an n-chunk of 128 tokens.
//   Mpart[chunk,h,d1,d2] = sum_{n in chunk} k_h[n,d1] * v_h[n,d2]
//   qsumpart[chunk, h*64+d] = sum_{n in chunk} q_h[n,d]
// grid (NCHUNK, 8), 256 threads. Thread owns (d1, 16 consecutive d2).
// ---------------------------------------------------------------------------
__global__ __launch_bounds__(256)
void head_reduce_kernel()
{
    const int chunk = blockIdx.x;
    const int h     = blockIdx.y;
    const int n0    = chunk * CHUNK;
    const int tid   = threadIdx.x;

    __shared__ float s[3][8][64];    // q,k,v rows for 8 tokens

    float acc[16];
#pragma unroll
    for (int j = 0; j < 16; j++) acc[j] = 0.0f;
    float qacc = 0.0f;

    const int d1  = tid >> 2;
    const int d2b = (tid & 3) << 4;

    for (int nt = 0; nt < CHUNK; nt += 8) {
        __syncthreads();
#pragma unroll
        for (int r = 0; r < 6; r++) {
            const int l   = tid + r * 256;      // 0..1535
            const int arr = l >> 9;             // 0=q,1=k,2=v
            const int nn  = (l >> 6) & 7;
            const int d   = l & 63;
            s[arr][nn][d] = g_qkv[(n0 + nt + nn) * E3 + arr * 512 + h * 64 + d];
        }
        __syncthreads();
#pragma unroll
        for (int nn = 0; nn < 8; nn++) {
            const float kd = s[1][nn][d1];
#pragma unroll
            for (int j = 0; j < 16; j++)
                acc[j] = fmaf(kd, s[2][nn][d2b + j], acc[j]);
            if (tid < 64) qacc += s[0][nn][tid];
        }
    }

    float* mp = &g_Mpart[((chunk * 8 + h) * 64 + d1) * 64 + d2b];
#pragma unroll
    for (int j = 0; j < 16; j += 4) {
        float4 o = { acc[j], acc[j + 1], acc[j + 2], acc[j + 3] };
        *(float4*)&mp[j] = o;
    }
    if (tid < 64) g_qsumpart[chunk * 512 + h * 64 + tid] = qacc;
}

// ---------------------------------------------------------------------------
// Kernel 3: deterministic reduction of chunk partials.
// blocks 0..127 -> M (32768 entries), block 128 -> qsum (512 entries).
// ---------------------------------------------------------------------------
__global__ __launch_bounds__(256)
void reduce_parts_kernel()
{
    if (blockIdx.x < 128) {
        const int idx = blockIdx.x * 256 + threadIdx.x;   // 0..32767
        float sum = 0.0f;
#pragma unroll
        for (int c = 0; c < NCHUNK; c++) sum += g_Mpart[c * 32768 + idx];
        g_M[idx] = sum;
    } else {
        for (int t = threadIdx.x; t < 512; t += 256) {
            float sum = 0.0f;
#pragma unroll
            for (int c = 0; c < NCHUNK; c++) sum += g_qsumpart[c * 512 + t];
            g_qsum[t] = sum;
        }
    }
}

// ---------------------------------------------------------------------------
// Kernel 4: outputs.
//   out[h,n,d2]  = scale * sum_d1 q_h[n,d1] * M_h[d1,d2]
//   coarse[h,n]  = scale * dot(qsum_h, k_h[n])
// grid (64 n-chunks of 64, 8 heads), 256 threads: thread = (n_local, d2 quarter)
// ---------------------------------------------------------------------------
__global__ __launch_bounds__(256)
void output_kernel(float* __restrict__ out)
{
    const int nb = blockIdx.x;
    const int h  = blockIdx.y;
    const int n0 = nb * 64;
    const int tid = threadIdx.x;

    __shared__ float Ms[64][64];
    __shared__ float qsm[64][65];    // padded q tile (avoid 8-way bank conflict)
    __shared__ float qsh[64];

#pragma unroll
    for (int r = 0; r < 16; r++) {
        const int l = tid + r * 256;
        Ms[l >> 6][l & 63] = g_M[h * 4096 + l];
        qsm[l >> 6][l & 63] = g_qkv[(n0 + (l >> 6)) * E3 + h * 64 + (l & 63)];
    }
    if (tid < 64) qsh[tid] = g_qsum[h * 64 + tid];
    __syncthreads();

    const int nl   = tid >> 2;       // 0..63
    const int part = tid & 3;
    const int d2b  = part << 4;
    const int n    = n0 + nl;

    float acc[16];
#pragma unroll
    for (int j = 0; j < 16; j++) acc[j] = 0.0f;

#pragma unroll
    for (int d1 = 0; d1 < 64; d1++) {
        const float qv = qsm[nl][d1];
#pragma unroll
        for (int j = 0; j < 16; j++)
            acc[j] = fmaf(qv, Ms[d1][d2b + j], acc[j]);
    }

    float* obase = out + 32768 + (((h << 12) + n) << 6) + d2b;
#pragma unroll
    for (int j = 0; j < 16; j += 4) {
        float4 o = { acc[j] * 0.125f, acc[j + 1] * 0.125f,
                     acc[j + 2] * 0.125f, acc[j + 3] * 0.125f };
        *(float4*)&obase[j] = o;
    }

    if (part == 0) {
        const float* krow = &g_qkv[n * E3 + 512 + h * 64];
        float c = 0.0f;
#pragma unroll
        for (int d = 0; d < 64; d++) c = fmaf(qsh[d], krow[d], c);
        out[(h << 12) + n] = c * 0.125f;
    }
}

// ---------------------------------------------------------------------------
extern "C" void kernel_launch(void* const* d_in, const int* in_sizes, int n_in,
                              void* d_out, int out_size)
{
    const float* x    = (const float*)d_in[0];   // [512, 4096]
    const float* Wq   = (const float*)d_in[1];   // [512, 1536]
    const float* bq   = (const float*)d_in[2];   // [1536]
    float* out = (float*)d_out;

    (void)in_sizes; (void)n_in; (void)out_size;

    dim3 g1(E3 / 128, NTOK / 128);   // 12 x 32
    qkv_gemm_kernel<<<g1, 256>>>(x, Wq, bq);

    dim3 g2(NCHUNK, 8);
    head_reduce_kernel<<<g2, 256>>>();

    reduce_parts_kernel<<<129, 256>>>();

    dim3 g4(64, 8);
    output_kernel<<<g4, 256>>>(out);
}

// round 7
// speedup vs baseline: 1.2316x; 1.2316x over previous
#include <cuda_runtime.h>
#include <cuda_bf16.h>
#include <cstdint>

// MHSA without softmax:
//   qkv = Xs @ W + b  (M=4096 tokens, K=512, N=1536)  <- mma.sync bf16 3-pass split
//   M_h = K_h^T V_h (64x64), qsum_h = sum_n q_h[n]
//   out[h,n,d]  = scale * q_h[n,:] @ M_h[:,d]
//   coarse[h,n] = scale * qsum_h . k_h[n]
// d_out: [coarse 8*4096][output 8*4096*64]

#define NTOK   4096
#define E3     1536
#define KSPLIT 1536          // 3 * 512 (hi*hi, hi*lo, lo*hi)
#define NCHUNK 32
#define CHUNK  (NTOK / NCHUNK)

__device__ float g_qkv[NTOK * E3];
__device__ float g_Mpart[NCHUNK * 8 * 64 * 64];
__device__ float g_qsumpart[NCHUNK * 512];
__device__ float g_M[8 * 64 * 64];
__device__ float g_qsum[512];
__device__ __nv_bfloat16 g_A[(size_t)NTOK * KSPLIT];   // [4096][1536] K-major
__device__ __nv_bfloat16 g_B[(size_t)E3 * KSPLIT];     // [1536][1536] K-major

// ---------------------------------------------------------------------------
// helpers (family-generic PTX only: cp.async / ldmatrix / mma.sync)
// ---------------------------------------------------------------------------
__device__ __forceinline__ uint32_t smem_u32(const void* p) {
    uint32_t a;
    asm("{ .reg .u64 t; cvta.to.shared.u64 t, %1; cvt.u32.u64 %0, t; }" : "=r"(a) : "l"(p));
    return a;
}

#define CP_ASYNC16(sa, gp) \
    asm volatile("cp.async.cg.shared.global [%0], [%1], 16;" :: "r"(sa), "l"(gp))
#define CP_COMMIT() asm volatile("cp.async.commit_group;")
#define CP_WAIT1()  asm volatile("cp.async.wait_group 1;")
#define CP_WAIT0()  asm volatile("cp.async.wait_group 0;")

#define LDMATRIX_X4(r0, r1, r2, r3, ad) \
    asm volatile("ldmatrix.sync.aligned.m8n8.x4.shared.b16 {%0,%1,%2,%3}, [%4];" \
        : "=r"(r0), "=r"(r1), "=r"(r2), "=r"(r3) : "r"(ad))

#define MMA_16816(d, a, b0, b1) \
    asm volatile("mma.sync.aligned.m16n8k16.row.col.f32.bf16.bf16.f32 " \
        "{%0,%1,%2,%3},{%4,%5,%6,%7},{%8,%9},{%0,%1,%2,%3};" \
        : "+f"((d)[0]), "+f"((d)[1]), "+f"((d)[2]), "+f"((d)[3]) \
        : "r"((a)[0]), "r"((a)[1]), "r"((a)[2]), "r"((a)[3]), "r"(b0), "r"(b1))

// ---------------------------------------------------------------------------
// conv A: X[512][4096] fp32 -> g_A[m][k] bf16, K-sections [hi | hi | lo]
// ---------------------------------------------------------------------------
__global__ void convA_kernel(const float* __restrict__ X)
{
    __shared__ float t[32][33];
    const int m0 = blockIdx.x * 32, e0 = blockIdx.y * 32;
    const int tx = threadIdx.x, ty = threadIdx.y;
#pragma unroll
    for (int i = 0; i < 4; i++)
        t[ty + 8 * i][tx] = X[(e0 + ty + 8 * i) * NTOK + m0 + tx];
    __syncthreads();
#pragma unroll
    for (int i = 0; i < 4; i++) {
        const int r = ty + 8 * i;
        const float v = t[tx][r];
        __nv_bfloat16 hi = __float2bfloat16(v);
        __nv_bfloat16 lo = __float2bfloat16(v - __bfloat162float(hi));
        const size_t base = (size_t)(m0 + r) * KSPLIT + e0 + tx;
        g_A[base] = hi; g_A[base + 512] = hi; g_A[base + 1024] = lo;
    }
}

// ---------------------------------------------------------------------------
// conv B: W[512][1536] fp32 -> g_B[j][k] bf16, K-sections [hi | lo | hi]
// ---------------------------------------------------------------------------
__global__ void convB_kernel(const float* __restrict__ W)
{
    __shared__ float t[32][33];
    const int j0 = blockIdx.x * 32, e0 = blockIdx.y * 32;
    const int tx = threadIdx.x, ty = threadIdx.y;
#pragma unroll
    for (int i = 0; i < 4; i++)
        t[ty + 8 * i][tx] = W[(e0 + ty + 8 * i) * E3 + j0 + tx];
    __syncthreads();
#pragma unroll
    for (int i = 0; i < 4; i++) {
        const int r = ty + 8 * i;
        const float v = t[tx][r];
        __nv_bfloat16 hi = __float2bfloat16(v);
        __nv_bfloat16 lo = __float2bfloat16(v - __bfloat162float(hi));
        const size_t base = (size_t)(j0 + r) * KSPLIT + e0 + tx;
        g_B[base] = hi; g_B[base + 512] = lo; g_B[base + 1024] = hi;
    }
}

// ---------------------------------------------------------------------------
// mma.sync bf16 GEMM: g_qkv[4096][1536] = A'[4096][1536] @ B'[1536][1536]^T + b
// CTA 128x128, 8 warps (2Mx4N, warp tile 64x32), K-stage 64, 2-stage cp.async.
// smem per stage: A 16KB + B 16KB, stored as 16B units (kq, row) with
// physical unit index kq*128 + (row^kq)  -> conflict-free STS + ldmatrix.
// ---------------------------------------------------------------------------
#define GEMM_SMEM (2 * 32768)

__global__ __launch_bounds__(256)
void qkv_mma_gemm(const float* __restrict__ bias)
{
    extern __shared__ char gsm[];
    const uint32_t base = smem_u32(gsm);
    const int tid = threadIdx.x;
    const int lane = tid & 31, wid = tid >> 5;
    const int bm = blockIdx.y * 128, bn = blockIdx.x * 128;
    const int wm = (wid & 1) * 64, wn = (wid >> 1) * 32;

    float acc[4][4][4];
#pragma unroll
    for (int i = 0; i < 4; i++)
#pragma unroll
        for (int j = 0; j < 4; j++)
#pragma unroll
            for (int r = 0; r < 4; r++) acc[i][j][r] = 0.0f;

    auto load_stage = [&](int st, int s) {
        const int k0 = st * 64;
        const uint32_t baseA = base + s * 32768;
        const uint32_t baseB = baseA + 16384;
#pragma unroll
        for (int i = 0; i < 4; i++) {
            const int u = i * 256 + tid;
            const int row = u >> 3, kq = u & 7;
            const uint32_t soff = (uint32_t)(kq * 128 + (row ^ kq)) * 16;
            CP_ASYNC16(baseA + soff, g_A + (size_t)(bm + row) * KSPLIT + k0 + kq * 8);
            CP_ASYNC16(baseB + soff, g_B + (size_t)(bn + row) * KSPLIT + k0 + kq * 8);
        }
        CP_COMMIT();
    };

    load_stage(0, 0);
    load_stage(1, 1);

    for (int it = 0; it < 24; ++it) {
        const int s = it & 1;
        if (it >= 22) { CP_WAIT0(); } else { CP_WAIT1(); }
        __syncthreads();

        const uint32_t baseA = base + s * 32768;
        const uint32_t baseB = baseA + 16384;

#pragma unroll
        for (int kk = 0; kk < 4; kk++) {
            uint32_t a[4][4], b[2][4];
            const int akq  = kk * 2 + (lane >> 4);
            const int arow = lane & 15;
#pragma unroll
            for (int mt = 0; mt < 4; mt++) {
                const int r = wm + mt * 16 + arow;
                const uint32_t ad = baseA + (uint32_t)(akq * 128 + (r ^ akq)) * 16;
                LDMATRIX_X4(a[mt][0], a[mt][1], a[mt][2], a[mt][3], ad);
            }
            const int bkq  = kk * 2 + ((lane >> 3) & 1);
            const int brow = ((lane >> 4) << 3) + (lane & 7);
#pragma unroll
            for (int nt = 0; nt < 2; nt++) {
                const int r = wn + nt * 16 + brow;
                const uint32_t bd = baseB + (uint32_t)(bkq * 128 + (r ^ bkq)) * 16;
                LDMATRIX_X4(b[nt][0], b[nt][1], b[nt][2], b[nt][3], bd);
            }
#pragma unroll
            for (int mt = 0; mt < 4; mt++)
#pragma unroll
                for (int n4 = 0; n4 < 4; n4++)
                    MMA_16816(acc[mt][n4], a[mt],
                              b[n4 >> 1][(n4 & 1) * 2], b[n4 >> 1][(n4 & 1) * 2 + 1]);
        }
        __syncthreads();
        if (it + 2 < 24) load_stage(it + 2, s);
    }

    // epilogue: + bias -> g_qkv fp32
    const int er = lane >> 2, ec = (lane & 3) * 2;
#pragma unroll
    for (int n4 = 0; n4 < 4; n4++) {
        const int c = bn + wn + n4 * 8 + ec;
        const float2 bv = *(const float2*)&bias[c];
#pragma unroll
        for (int mt = 0; mt < 4; mt++) {
            const int r = bm + wm + mt * 16 + er;
            float2 o0 = { acc[mt][n4][0] + bv.x, acc[mt][n4][1] + bv.y };
            *(float2*)&g_qkv[(size_t)r * E3 + c] = o0;
            float2 o1 = { acc[mt][n4][2] + bv.x, acc[mt][n4][3] + bv.y };
            *(float2*)&g_qkv[(size_t)(r + 8) * E3 + c] = o1;
        }
    }
}

// ---------------------------------------------------------------------------
// per-head partial reductions: Mpart[c,h] = sum_{n in chunk} k_h[n]^T v_h[n]
// ---------------------------------------------------------------------------
__global__ __launch_bounds__(256)
void head_reduce_kernel()
{
    const int chunk = blockIdx.x;
    const int h     = blockIdx.y;
    const int n0    = chunk * CHUNK;
    const int tid   = threadIdx.x;

    __shared__ float s[3][8][64];

    float acc[16];
#pragma unroll
    for (int j = 0; j < 16; j++) acc[j] = 0.0f;
    float qacc = 0.0f;

    const int d1  = tid >> 2;
    const int d2b = (tid & 3) << 4;

    for (int nt = 0; nt < CHUNK; nt += 8) {
        __syncthreads();
#pragma unroll
        for (int r = 0; r < 6; r++) {
            const int l   = tid + r * 256;
            const int arr = l >> 9;
            const int nn  = (l >> 6) & 7;
            const int d   = l & 63;
            s[arr][nn][d] = g_qkv[(size_t)(n0 + nt + nn) * E3 + arr * 512 + h * 64 + d];
        }
        __syncthreads();
#pragma unroll
        for (int nn = 0; nn < 8; nn++) {
            const float kd = s[1][nn][d1];
#pragma unroll
            for (int j = 0; j < 16; j++)
                acc[j] = fmaf(kd, s[2][nn][d2b + j], acc[j]);
            if (tid < 64) qacc += s[0][nn][tid];
        }
    }

    float* mp = &g_Mpart[((chunk * 8 + h) * 64 + d1) * 64 + d2b];
#pragma unroll
    for (int j = 0; j < 16; j += 4) {
        float4 o = { acc[j], acc[j + 1], acc[j + 2], acc[j + 3] };
        *(float4*)&mp[j] = o;
    }
    if (tid < 64) g_qsumpart[chunk * 512 + h * 64 + tid] = qacc;
}

__global__ __launch_bounds__(256)
void reduce_parts_kernel()
{
    if (blockIdx.x < 128) {
        const int idx = blockIdx.x * 256 + threadIdx.x;
        float sum = 0.0f;
#pragma unroll
        for (int c = 0; c < NCHUNK; c++) sum += g_Mpart[c * 32768 + idx];
        g_M[idx] = sum;
    } else {
        for (int t = threadIdx.x; t < 512; t += 256) {
            float sum = 0.0f;
#pragma unroll
            for (int c = 0; c < NCHUNK; c++) sum += g_qsumpart[c * 512 + t];
            g_qsum[t] = sum;
        }
    }
}

// ---------------------------------------------------------------------------
// output: register-blocked (8n x 4d2 per thread). grid (32, 8), 256 threads.
// ---------------------------------------------------------------------------
__global__ __launch_bounds__(256)
void output_kernel(float* __restrict__ out)
{
    extern __shared__ float osm[];
    float (*Ms)[64] = (float(*)[64])osm;            // 64 x 64
    float (*qs)[64] = (float(*)[64])(osm + 4096);   // 128 x 64

    const int n0 = blockIdx.x * 128;
    const int h  = blockIdx.y;
    const int t  = threadIdx.x;

#pragma unroll
    for (int r = 0; r < 4; r++) {
        const int l = t + r * 256;
        *(float4*)&Ms[l >> 4][(l & 15) * 4] =
            *(const float4*)&g_M[h * 4096 + (l >> 4) * 64 + (l & 15) * 4];
    }
#pragma unroll
    for (int r = 0; r < 8; r++) {
        const int l = t + r * 256;
        *(float4*)&qs[l >> 4][(l & 15) * 4] =
            *(const float4*)&g_qkv[(size_t)(n0 + (l >> 4)) * E3 + h * 64 + (l & 15) * 4];
    }
    __syncthreads();

    const int tx = t & 15;
    const int ty = t >> 4;

    float acc[8][4];
#pragma unroll
    for (int i = 0; i < 8; i++)
#pragma unroll
        for (int j = 0; j < 4; j++) acc[i][j] = 0.0f;

#pragma unroll
    for (int d1 = 0; d1 < 64; d1++) {
        const float4 m4 = *(const float4*)&Ms[d1][tx * 4];
#pragma unroll
        for (int i = 0; i < 8; i++) {
            const float qv = qs[ty * 8 + i][d1];
            acc[i][0] = fmaf(qv, m4.x, acc[i][0]);
            acc[i][1] = fmaf(qv, m4.y, acc[i][1]);
            acc[i][2] = fmaf(qv, m4.z, acc[i][2]);
            acc[i][3] = fmaf(qv, m4.w, acc[i][3]);
        }
    }

#pragma unroll
    for (int i = 0; i < 8; i++) {
        const int n = n0 + ty * 8 + i;
        float4 o = { acc[i][0] * 0.125f, acc[i][1] * 0.125f,
                     acc[i][2] * 0.125f, acc[i][3] * 0.125f };
        *(float4*)&out[32768 + (size_t)((h << 12) + n) * 64 + tx * 4] = o;
    }
}

// ---------------------------------------------------------------------------
// coarse[h,n] = scale * qsum_h . k_h[n]
// ---------------------------------------------------------------------------
__global__ __launch_bounds__(256)
void coarse_kernel(float* __restrict__ out)
{
    __shared__ float qs[512];
    for (int l = threadIdx.x; l < 512; l += 256) qs[l] = g_qsum[l];
    __syncthreads();

    const int gid = blockIdx.x * 256 + threadIdx.x;
    const int h = gid >> 12, n = gid & 4095;
    const float4* kp = (const float4*)&g_qkv[(size_t)n * E3 + 512 + h * 64];
    const float4* qp = (const float4*)&qs[h * 64];
    float c = 0.0f;
#pragma unroll
    for (int i = 0; i < 16; i++) {
        const float4 k4 = kp[i], q4 = qp[i];
        c = fmaf(q4.x, k4.x, c); c = fmaf(q4.y, k4.y, c);
        c = fmaf(q4.z, k4.z, c); c = fmaf(q4.w, k4.w, c);
    }
    out[gid] = c * 0.125f;
}

// ---------------------------------------------------------------------------
extern "C" void kernel_launch(void* const* d_in, const int* in_sizes, int n_in,
                              void* d_out, int out_size)
{
    const float* x  = (const float*)d_in[0];   // [512, 4096]
    const float* Wq = (const float*)d_in[1];   // [512, 1536]
    const float* bq = (const float*)d_in[2];   // [1536]
    float* out = (float*)d_out;
    (void)in_sizes; (void)n_in; (void)out_size;

    cudaFuncSetAttribute(qkv_mma_gemm, cudaFuncAttributeMaxDynamicSharedMemorySize, GEMM_SMEM);
    cudaFuncSetAttribute(output_kernel, cudaFuncAttributeMaxDynamicSharedMemorySize, 49152);

    convA_kernel<<<dim3(128, 16), dim3(32, 8)>>>(x);
    convB_kernel<<<dim3(48, 16), dim3(32, 8)>>>(Wq);

    qkv_mma_gemm<<<dim3(12, 32), 256, GEMM_SMEM>>>(bq);

    head_reduce_kernel<<<dim3(NCHUNK, 8), 256>>>();
    reduce_parts_kernel<<<129, 256>>>();

    output_kernel<<<dim3(32, 8), 256, 49152>>>(out);
    coarse_kernel<<<128, 256>>>(out);
}

// round 8
// speedup vs baseline: 1.2465x; 1.0121x over previous
#include <cuda_runtime.h>
#include <cuda_bf16.h>
#include <cstdint>

// MHSA without softmax:
//   qkv = Xs @ W + b  (M=4096, K=512, N=1536)  <- mma.sync bf16 3-pass split
//   M_h = K_h^T V_h (64x64), qsum_h = sum_n q_h[n]
//   out[h,n,d]  = scale * q_h[n,:] @ M_h[:,d]
//   coarse[h,n] = scale * qsum_h . k_h[n]
// d_out: [coarse 8*4096][output 8*4096*64]

#define NTOK   4096
#define E3     1536
#define KSPLIT 1536          // 3 * 512 (hi*hi, hi*lo, lo*hi)
#define NCHUNK 64
#define CHUNK  (NTOK / NCHUNK)   // 64 tokens per chunk

__device__ float g_qkv[NTOK * E3];
__device__ float g_Mpart[NCHUNK * 8 * 64 * 64];
__device__ float g_qsumpart[NCHUNK * 512];
__device__ float g_M[8 * 64 * 64];
__device__ float g_qsum[512];
__device__ __nv_bfloat16 g_A[(size_t)NTOK * KSPLIT];   // [4096][1536] K-major
__device__ __nv_bfloat16 g_B[(size_t)E3 * KSPLIT];     // [1536][1536] K-major

// ---------------------------------------------------------------------------
// helpers (family-generic PTX only: cp.async / ldmatrix / mma.sync)
// ---------------------------------------------------------------------------
__device__ __forceinline__ uint32_t smem_u32(const void* p) {
    uint32_t a;
    asm("{ .reg .u64 t; cvta.to.shared.u64 t, %1; cvt.u32.u64 %0, t; }" : "=r"(a) : "l"(p));
    return a;
}

#define CP_ASYNC16(sa, gp) \
    asm volatile("cp.async.cg.shared.global [%0], [%1], 16;" :: "r"(sa), "l"(gp))
#define CP_COMMIT() asm volatile("cp.async.commit_group;")
#define CP_WAIT1()  asm volatile("cp.async.wait_group 1;")
#define CP_WAIT0()  asm volatile("cp.async.wait_group 0;")

#define LDMATRIX_X4(r0, r1, r2, r3, ad) \
    asm volatile("ldmatrix.sync.aligned.m8n8.x4.shared.b16 {%0,%1,%2,%3}, [%4];" \
        : "=r"(r0), "=r"(r1), "=r"(r2), "=r"(r3) : "r"(ad))

#define MMA_16816(d, a, b0, b1) \
    asm volatile("mma.sync.aligned.m16n8k16.row.col.f32.bf16.bf16.f32 " \
        "{%0,%1,%2,%3},{%4,%5,%6,%7},{%8,%9},{%0,%1,%2,%3};" \
        : "+f"((d)[0]), "+f"((d)[1]), "+f"((d)[2]), "+f"((d)[3]) \
        : "r"((a)[0]), "r"((a)[1]), "r"((a)[2]), "r"((a)[3]), "r"(b0), "r"(b1))

// ---------------------------------------------------------------------------
// conv A: X[512][4096] fp32 -> g_A[m][k] bf16, K-sections [hi | hi | lo]
// block: 64 e x 32 m. Transpose via smem; 16B vectorized section stores.
// ---------------------------------------------------------------------------
__global__ __launch_bounds__(256)
void convA_kernel(const float* __restrict__ X)
{
    __shared__ float t[64][33];
    const int m0 = blockIdx.x * 32, e0 = blockIdx.y * 64;
    const int tx = threadIdx.x & 31, ty = threadIdx.x >> 5;

#pragma unroll
    for (int i = 0; i < 8; i++)
        t[ty + 8 * i][tx] = X[(size_t)(e0 + ty + 8 * i) * NTOK + m0 + tx];
    __syncthreads();

    const int m  = threadIdx.x >> 3;        // 0..31
    const int eg = (threadIdx.x & 7) * 8;   // 0..56
    __nv_bfloat16 hi[8], lo[8];
#pragma unroll
    for (int j = 0; j < 8; j++) {
        const float v = t[eg + j][m];
        hi[j] = __float2bfloat16(v);
        lo[j] = __float2bfloat16(v - __bfloat162float(hi[j]));
    }
    const size_t base = (size_t)(m0 + m) * KSPLIT + e0 + eg;
    *(uint4*)&g_A[base]        = *(uint4*)hi;
    *(uint4*)&g_A[base + 512]  = *(uint4*)hi;
    *(uint4*)&g_A[base + 1024] = *(uint4*)lo;
}

// ---------------------------------------------------------------------------
// conv B: W[512][1536] fp32 -> g_B[j][k] bf16, K-sections [hi | lo | hi]
// ---------------------------------------------------------------------------
__global__ __launch_bounds__(256)
void convB_kernel(const float* __restrict__ W)
{
    __shared__ float t[64][33];
    const int j0 = blockIdx.x * 32, e0 = blockIdx.y * 64;
    const int tx = threadIdx.x & 31, ty = threadIdx.x >> 5;

#pragma unroll
    for (int i = 0; i < 8; i++)
        t[ty + 8 * i][tx] = W[(size_t)(e0 + ty + 8 * i) * E3 + j0 + tx];
    __syncthreads();

    const int jj = threadIdx.x >> 3;
    const int eg = (threadIdx.x & 7) * 8;
    __nv_bfloat16 hi[8], lo[8];
#pragma unroll
    for (int j = 0; j < 8; j++) {
        const float v = t[eg + j][jj];
        hi[j] = __float2bfloat16(v);
        lo[j] = __float2bfloat16(v - __bfloat162float(hi[j]));
    }
    const size_t base = (size_t)(j0 + jj) * KSPLIT + e0 + eg;
    *(uint4*)&g_B[base]        = *(uint4*)hi;
    *(uint4*)&g_B[base + 512]  = *(uint4*)lo;
    *(uint4*)&g_B[base + 1024] = *(uint4*)hi;
}

// ---------------------------------------------------------------------------
// mma.sync bf16 GEMM: g_qkv[4096][1536] = A'[4096][1536] @ B'[1536][1536]^T + b
// CTA 128x128, 8 warps (2Mx4N, warp tile 64x32), K-stage 64, 2-stage cp.async.
// ---------------------------------------------------------------------------
#define GEMM_SMEM (2 * 32768)

__global__ __launch_bounds__(256)
void qkv_mma_gemm(const float* __restrict__ bias)
{
    extern __shared__ char gsm[];
    const uint32_t base = smem_u32(gsm);
    const int tid = threadIdx.x;
    const int lane = tid & 31, wid = tid >> 5;
    const int bm = blockIdx.y * 128, bn = blockIdx.x * 128;
    const int wm = (wid & 1) * 64, wn = (wid >> 1) * 32;

    float acc[4][4][4];
#pragma unroll
    for (int i = 0; i < 4; i++)
#pragma unroll
        for (int j = 0; j < 4; j++)
#pragma unroll
            for (int r = 0; r < 4; r++) acc[i][j][r] = 0.0f;

    auto load_stage = [&](int st, int s) {
        const int k0 = st * 64;
        const uint32_t baseA = base + s * 32768;
        const uint32_t baseB = baseA + 16384;
#pragma unroll
        for (int i = 0; i < 4; i++) {
            const int u = i * 256 + tid;
            const int row = u >> 3, kq = u & 7;
            const uint32_t soff = (uint32_t)(kq * 128 + (row ^ kq)) * 16;
            CP_ASYNC16(baseA + soff, g_A + (size_t)(bm + row) * KSPLIT + k0 + kq * 8);
            CP_ASYNC16(baseB + soff, g_B + (size_t)(bn + row) * KSPLIT + k0 + kq * 8);
        }
        CP_COMMIT();
    };

    load_stage(0, 0);
    load_stage(1, 1);

    for (int it = 0; it < 24; ++it) {
        const int s = it & 1;
        if (it >= 22) { CP_WAIT0(); } else { CP_WAIT1(); }
        __syncthreads();

        const uint32_t baseA = base + s * 32768;
        const uint32_t baseB = baseA + 16384;

#pragma unroll
        for (int kk = 0; kk < 4; kk++) {
            uint32_t a[4][4], b[2][4];
            const int akq  = kk * 2 + (lane >> 4);
            const int arow = lane & 15;
#pragma unroll
            for (int mt = 0; mt < 4; mt++) {
                const int r = wm + mt * 16 + arow;
                const uint32_t ad = baseA + (uint32_t)(akq * 128 + (r ^ akq)) * 16;
                LDMATRIX_X4(a[mt][0], a[mt][1], a[mt][2], a[mt][3], ad);
            }
            const int bkq  = kk * 2 + ((lane >> 3) & 1);
            const int brow = ((lane >> 4) << 3) + (lane & 7);
#pragma unroll
            for (int nt = 0; nt < 2; nt++) {
                const int r = wn + nt * 16 + brow;
                const uint32_t bd = baseB + (uint32_t)(bkq * 128 + (r ^ bkq)) * 16;
                LDMATRIX_X4(b[nt][0], b[nt][1], b[nt][2], b[nt][3], bd);
            }
#pragma unroll
            for (int mt = 0; mt < 4; mt++)
#pragma unroll
                for (int n4 = 0; n4 < 4; n4++)
                    MMA_16816(acc[mt][n4], a[mt],
                              b[n4 >> 1][(n4 & 1) * 2], b[n4 >> 1][(n4 & 1) * 2 + 1]);
        }
        __syncthreads();
        if (it + 2 < 24) load_stage(it + 2, s);
    }

    // epilogue: + bias -> g_qkv fp32
    const int er = lane >> 2, ec = (lane & 3) * 2;
#pragma unroll
    for (int n4 = 0; n4 < 4; n4++) {
        const int c = bn + wn + n4 * 8 + ec;
        const float2 bv = *(const float2*)&bias[c];
#pragma unroll
        for (int mt = 0; mt < 4; mt++) {
            const int r = bm + wm + mt * 16 + er;
            float2 o0 = { acc[mt][n4][0] + bv.x, acc[mt][n4][1] + bv.y };
            *(float2*)&g_qkv[(size_t)r * E3 + c] = o0;
            float2 o1 = { acc[mt][n4][2] + bv.x, acc[mt][n4][3] + bv.y };
            *(float2*)&g_qkv[(size_t)(r + 8) * E3 + c] = o1;
        }
    }
}

// ---------------------------------------------------------------------------
// head reduce: chunk = 64 tokens. grid (64, 8), 256 threads, 50 KB dyn smem.
//   Mpart[c,h,d1,d2] = sum_{n in chunk} k_h[n,d1] * v_h[n,d2]
//   qsumpart[c, h*64+d] = sum_{n in chunk} q_h[n,d]
// One barrier; float4 staging; register-blocked 16-wide inner FMA.
// ---------------------------------------------------------------------------
#define HR_SMEM (13312 * 4)   // q 4096 + k 4096 + v 4096 + part 1024 floats

__global__ __launch_bounds__(256)
void head_reduce_kernel()
{
    extern __shared__ float hs[];   // [0)q [4096)k [8192)v [12288)part
    const int chunk = blockIdx.x;
    const int h     = blockIdx.y;
    const int n0    = chunk * CHUNK;
    const int tid   = threadIdx.x;

#pragma unroll
    for (int arr = 0; arr < 3; arr++) {
#pragma unroll
        for (int r = 0; r < 4; r++) {
            const int l = tid + r * 256;          // float4 idx 0..1023
            const int row = l >> 4, c = (l & 15) * 4;
            *(float4*)&hs[arr * 4096 + row * 64 + c] =
                *(const float4*)&g_qkv[(size_t)(n0 + row) * E3 + arr * 512 + h * 64 + c];
        }
    }
    __syncthreads();

    // qsum partial: thread (grp = tid>>6, d = tid&63) sums 16 tokens
    {
        const int d = tid & 63, grp = tid >> 6;
        float qa = 0.0f;
#pragma unroll
        for (int nn = 0; nn < 16; nn++)
            qa += hs[(grp * 16 + nn) * 64 + d];
        hs[12288 + grp * 64 + d] = qa;
    }

    // K^T V outer product: thread (d1 = tid>>2, 16 consecutive d2)
    const int d1  = tid >> 2;
    const int d2b = (tid & 3) << 4;
    float acc[16];
#pragma unroll
    for (int j = 0; j < 16; j++) acc[j] = 0.0f;

#pragma unroll 4
    for (int n = 0; n < 64; n++) {
        const float kd = hs[4096 + n * 64 + d1];
        const float4 v0 = *(const float4*)&hs[8192 + n * 64 + d2b];
        const float4 v1 = *(const float4*)&hs[8192 + n * 64 + d2b + 4];
        const float4 v2 = *(const float4*)&hs[8192 + n * 64 + d2b + 8];
        const float4 v3 = *(const float4*)&hs[8192 + n * 64 + d2b + 12];
        acc[0]  = fmaf(kd, v0.x, acc[0]);  acc[1]  = fmaf(kd, v0.y, acc[1]);
        acc[2]  = fmaf(kd, v0.z, acc[2]);  acc[3]  = fmaf(kd, v0.w, acc[3]);
        acc[4]  = fmaf(kd, v1.x, acc[4]);  acc[5]  = fmaf(kd, v1.y, acc[5]);
        acc[6]  = fmaf(kd, v1.z, acc[6]);  acc[7]  = fmaf(kd, v1.w, acc[7]);
        acc[8]  = fmaf(kd, v2.x, acc[8]);  acc[9]  = fmaf(kd, v2.y, acc[9]);
        acc[10] = fmaf(kd, v2.z, acc[10]); acc[11] = fmaf(kd, v2.w, acc[11]);
        acc[12] = fmaf(kd, v3.x, acc[12]); acc[13] = fmaf(kd, v3.y, acc[13]);
        acc[14] = fmaf(kd, v3.z, acc[14]); acc[15] = fmaf(kd, v3.w, acc[15]);
    }

    float* mp = &g_Mpart[((chunk * 8 + h) * 64 + d1) * 64 + d2b];
#pragma unroll
    for (int j = 0; j < 16; j += 4) {
        float4 o = { acc[j], acc[j + 1], acc[j + 2], acc[j + 3] };
        *(float4*)&mp[j] = o;
    }

    __syncthreads();
    if (tid < 64) {
        float s = hs[12288 + tid] + hs[12288 + 64 + tid]
                + hs[12288 + 128 + tid] + hs[12288 + 192 + tid];
        g_qsumpart[chunk * 512 + h * 64 + tid] = s;
    }
}

__global__ __launch_bounds__(256)
void reduce_parts_kernel()
{
    if (blockIdx.x < 128) {
        const int idx = blockIdx.x * 256 + threadIdx.x;
        float sum = 0.0f;
#pragma unroll
        for (int c = 0; c < NCHUNK; c++) sum += g_Mpart[c * 32768 + idx];
        g_M[idx] = sum;
    } else {
        for (int t = threadIdx.x; t < 512; t += 256) {
            float sum = 0.0f;
#pragma unroll
            for (int c = 0; c < NCHUNK; c++) sum += g_qsumpart[c * 512 + t];
            g_qsum[t] = sum;
        }
    }
}

// ---------------------------------------------------------------------------
// output: register-blocked (8n x 4d2 per thread). grid (32, 8), 256 threads.
// ---------------------------------------------------------------------------
__global__ __launch_bounds__(256)
void output_kernel(float* __restrict__ out)
{
    extern __shared__ float osm[];
    float (*Ms)[64] = (float(*)[64])osm;            // 64 x 64
    float (*qs)[64] = (float(*)[64])(osm + 4096);   // 128 x 64

    const int n0 = blockIdx.x * 128;
    const int h  = blockIdx.y;
    const int t  = threadIdx.x;

#pragma unroll
    for (int r = 0; r < 4; r++) {
        const int l = t + r * 256;
        *(float4*)&Ms[l >> 4][(l & 15) * 4] =
            *(const float4*)&g_M[h * 4096 + (l >> 4) * 64 + (l & 15) * 4];
    }
#pragma unroll
    for (int r = 0; r < 8; r++) {
        const int l = t + r * 256;
        *(float4*)&qs[l >> 4][(l & 15) * 4] =
            *(const float4*)&g_qkv[(size_t)(n0 + (l >> 4)) * E3 + h * 64 + (l & 15) * 4];
    }
    __syncthreads();

    const int tx = t & 15;
    const int ty = t >> 4;

    float acc[8][4];
#pragma unroll
    for (int i = 0; i < 8; i++)
#pragma unroll
        for (int j = 0; j < 4; j++) acc[i][j] = 0.0f;

#pragma unroll
    for (int d1 = 0; d1 < 64; d1++) {
        const float4 m4 = *(const float4*)&Ms[d1][tx * 4];
#pragma unroll
        for (int i = 0; i < 8; i++) {
            const float qv = qs[ty * 8 + i][d1];
            acc[i][0] = fmaf(qv, m4.x, acc[i][0]);
            acc[i][1] = fmaf(qv, m4.y, acc[i][1]);
            acc[i][2] = fmaf(qv, m4.z, acc[i][2]);
            acc[i][3] = fmaf(qv, m4.w, acc[i][3]);
        }
    }

#pragma unroll
    for (int i = 0; i < 8; i++) {
        const int n = n0 + ty * 8 + i;
        float4 o = { acc[i][0] * 0.125f, acc[i][1] * 0.125f,
                     acc[i][2] * 0.125f, acc[i][3] * 0.125f };
        *(float4*)&out[32768 + (size_t)((h << 12) + n) * 64 + tx * 4] = o;
    }
}

// ---------------------------------------------------------------------------
// coarse[h,n] = scale * qsum_h . k_h[n]
// ---------------------------------------------------------------------------
__global__ __launch_bounds__(256)
void coarse_kernel(float* __restrict__ out)
{
    __shared__ float qs[512];
    for (int l = threadIdx.x; l < 512; l += 256) qs[l] = g_qsum[l];
    __syncthreads();

    const int gid = blockIdx.x * 256 + threadIdx.x;
    const int h = gid >> 12, n = gid & 4095;
    const float4* kp = (const float4*)&g_qkv[(size_t)n * E3 + 512 + h * 64];
    const float4* qp = (const float4*)&qs[h * 64];
    float c = 0.0f;
#pragma unroll
    for (int i = 0; i < 16; i++) {
        const float4 k4 = kp[i], q4 = qp[i];
        c = fmaf(q4.x, k4.x, c); c = fmaf(q4.y, k4.y, c);
        c = fmaf(q4.z, k4.z, c); c = fmaf(q4.w, k4.w, c);
    }
    out[gid] = c * 0.125f;
}

// ---------------------------------------------------------------------------
extern "C" void kernel_launch(void* const* d_in, const int* in_sizes, int n_in,
                              void* d_out, int out_size)
{
    const float* x  = (const float*)d_in[0];   // [512, 4096]
    const float* Wq = (const float*)d_in[1];   // [512, 1536]
    const float* bq = (const float*)d_in[2];   // [1536]
    float* out = (float*)d_out;
    (void)in_sizes; (void)n_in; (void)out_size;

    cudaFuncSetAttribute(qkv_mma_gemm, cudaFuncAttributeMaxDynamicSharedMemorySize, GEMM_SMEM);
    cudaFuncSetAttribute(output_kernel, cudaFuncAttributeMaxDynamicSharedMemorySize, 49152);
    cudaFuncSetAttribute(head_reduce_kernel, cudaFuncAttributeMaxDynamicSharedMemorySize, HR_SMEM);

    convA_kernel<<<dim3(128, 8), 256>>>(x);
    convB_kernel<<<dim3(48, 8), 256>>>(Wq);

    qkv_mma_gemm<<<dim3(12, 32), 256, GEMM_SMEM>>>(bq);

    head_reduce_kernel<<<dim3(NCHUNK, 8), 256, HR_SMEM>>>();
    reduce_parts_kernel<<<129, 256>>>();

    output_kernel<<<dim3(32, 8), 256, 49152>>>(out);
    coarse_kernel<<<128, 256>>>(out);
}

// round 9
// speedup vs baseline: 2.7983x; 2.2450x over previous
#include <cuda_runtime.h>
#include <cuda_bf16.h>
#include <cstdint>

// MHSA without softmax:
//   qkv = Xs @ W + b  (M=4096, K=512, N=1536)  <- mma.sync TF32 single-pass
//   M_h = K_h^T V_h (64x64), qsum_h = sum_n q_h[n]
//   out[h,n,d]  = scale * q_h[n,:] @ M_h[:,d]
//   coarse[h,n] = scale * qsum_h . k_h[n]
// d_out: [coarse 8*4096][output 8*4096*64]

#define NTOK   4096
#define E3     1536
#define NCHUNK 64
#define CHUNK  (NTOK / NCHUNK)   // 64 tokens per chunk

__device__ float g_qkv[NTOK * E3];
__device__ float g_Mpart[NCHUNK * 8 * 64 * 64];
__device__ float g_qsumpart[NCHUNK * 512];
__device__ float g_M[8 * 64 * 64];
__device__ float g_qsum[512];

// ---------------------------------------------------------------------------
// helpers (family-generic PTX only: cp.async / cvt.tf32 / mma.sync)
// ---------------------------------------------------------------------------
__device__ __forceinline__ uint32_t smem_u32(const void* p) {
    uint32_t a;
    asm("{ .reg .u64 t; cvta.to.shared.u64 t, %1; cvt.u32.u64 %0, t; }" : "=r"(a) : "l"(p));
    return a;
}

#define CP_ASYNC16(sa, gp) \
    asm volatile("cp.async.cg.shared.global [%0], [%1], 16;" :: "r"(sa), "l"(gp))
#define CP_COMMIT() asm volatile("cp.async.commit_group;")
#define CP_WAIT1()  asm volatile("cp.async.wait_group 1;")
#define CP_WAIT0()  asm volatile("cp.async.wait_group 0;")

__device__ __forceinline__ uint32_t f2tf32(float f) {
    uint32_t r;
    asm("cvt.rna.tf32.f32 %0, %1;" : "=r"(r) : "f"(f));
    return r;
}

#define MMA_TF32(d, a, b0, b1) \
    asm volatile("mma.sync.aligned.m16n8k8.row.col.f32.tf32.tf32.f32 " \
        "{%0,%1,%2,%3},{%4,%5,%6,%7},{%8,%9},{%0,%1,%2,%3};" \
        : "+f"((d)[0]), "+f"((d)[1]), "+f"((d)[2]), "+f"((d)[3]) \
        : "r"((a)[0]), "r"((a)[1]), "r"((a)[2]), "r"((a)[3]), "r"(b0), "r"(b1))

// ---------------------------------------------------------------------------
// TF32 GEMM: g_qkv[4096][1536] = X^T[4096][512] @ W[512][1536] + bias
// CTA 128x128, 8 warps (2Mx4N, warp tile 64x32), BK=16, 3-stage cp.async.
// smem per stage: As[16][136] + Bs[16][136] fp32 (pad 136 -> conflict-free
// fragment LDS: bank = (8k + m) % 32 covers all 32 banks).
// A[m][k] = X[k][m] (m contiguous per k-row), B[k][n] = W[k][n] (n contiguous).
// ---------------------------------------------------------------------------
#define SSTRIDE   136
#define STAGE_B   (2 * 16 * SSTRIDE * 4)      // 17408 bytes (A then B)
#define GEMM_SMEM (3 * STAGE_B)               // 52224 bytes

__global__ __launch_bounds__(256)
void qkv_tf32_gemm(const float* __restrict__ X,
                   const float* __restrict__ W,
                   const float* __restrict__ bias)
{
    extern __shared__ char gsm[];
    const uint32_t base = smem_u32(gsm);
    const int tid = threadIdx.x;
    const int lane = tid & 31, wid = tid >> 5;
    const int bm = blockIdx.y * 128, bn = blockIdx.x * 128;
    const int wm = (wid & 1) * 64, wn = (wid >> 1) * 32;

    float acc[4][4][4];
#pragma unroll
    for (int i = 0; i < 4; i++)
#pragma unroll
        for (int j = 0; j < 4; j++)
#pragma unroll
            for (int r = 0; r < 4; r++) acc[i][j][r] = 0.0f;

    auto load_stage = [&](int it, int s) {
        const int k0 = it * 16;
        const uint32_t sa = base + s * STAGE_B;
#pragma unroll
        for (int i = 0; i < 2; i++) {
            const int u = i * 256 + tid;
            const int row = u >> 5;           // k-row 0..15
            const int c = (u & 31) * 4;       // float col 0..124
            CP_ASYNC16(sa + (uint32_t)(row * SSTRIDE + c) * 4,
                       X + (size_t)(k0 + row) * NTOK + bm + c);
            CP_ASYNC16(sa + 16 * SSTRIDE * 4 + (uint32_t)(row * SSTRIDE + c) * 4,
                       W + (size_t)(k0 + row) * E3 + bn + c);
        }
        CP_COMMIT();
    };

    load_stage(0, 0);
    load_stage(1, 1);

    for (int it = 0; it < 32; ++it) {
        if (it >= 30) { CP_WAIT0(); } else { CP_WAIT1(); }
        __syncthreads();
        if (it + 2 < 32) load_stage(it + 2, (it + 2) % 3);

        const float* As = (const float*)(gsm + (it % 3) * STAGE_B);
        const float* Bs = As + 16 * SSTRIDE;

#pragma unroll
        for (int kk = 0; kk < 2; kk++) {
            const int kb = kk * 8 + (lane & 3);
            uint32_t a[4][4], b[4][2];
#pragma unroll
            for (int mt = 0; mt < 4; mt++) {
                const int m = wm + mt * 16 + (lane >> 2);
                a[mt][0] = f2tf32(As[kb * SSTRIDE + m]);
                a[mt][1] = f2tf32(As[kb * SSTRIDE + m + 8]);
                a[mt][2] = f2tf32(As[(kb + 4) * SSTRIDE + m]);
                a[mt][3] = f2tf32(As[(kb + 4) * SSTRIDE + m + 8]);
            }
#pragma unroll
            for (int n8 = 0; n8 < 4; n8++) {
                const int n = wn + n8 * 8 + (lane >> 2);
                b[n8][0] = f2tf32(Bs[kb * SSTRIDE + n]);
                b[n8][1] = f2tf32(Bs[(kb + 4) * SSTRIDE + n]);
            }
#pragma unroll
            for (int mt = 0; mt < 4; mt++)
#pragma unroll
                for (int n8 = 0; n8 < 4; n8++)
                    MMA_TF32(acc[mt][n8], a[mt], b[n8][0], b[n8][1]);
        }
        __syncthreads();
    }

    // epilogue: + bias -> g_qkv fp32
    const int er = lane >> 2, ec = (lane & 3) * 2;
#pragma unroll
    for (int n8 = 0; n8 < 4; n8++) {
        const int c = bn + wn + n8 * 8 + ec;
        const float2 bv = *(const float2*)&bias[c];
#pragma unroll
        for (int mt = 0; mt < 4; mt++) {
            const int r = bm + wm + mt * 16 + er;
            float2 o0 = { acc[mt][n8][0] + bv.x, acc[mt][n8][1] + bv.y };
            *(float2*)&g_qkv[(size_t)r * E3 + c] = o0;
            float2 o1 = { acc[mt][n8][2] + bv.x, acc[mt][n8][3] + bv.y };
            *(float2*)&g_qkv[(size_t)(r + 8) * E3 + c] = o1;
        }
    }
}

// ---------------------------------------------------------------------------
// head reduce: chunk = 64 tokens. grid (64, 8), 256 threads, 52 KB dyn smem.
//   Mpart[c,h,d1,d2] = sum_{n in chunk} k_h[n,d1] * v_h[n,d2]
//   qsumpart[c, h*64+d] = sum_{n in chunk} q_h[n,d]
// Thread tile 4 d1 x 4 d2: 2x LDS.128 per 16 FMA.
// ---------------------------------------------------------------------------
#define HR_SMEM (13312 * 4)   // q 4096 + k 4096 + v 4096 + part 1024 floats

__global__ __launch_bounds__(256)
void head_reduce_kernel()
{
    extern __shared__ float hs[];   // [0)q [4096)k [8192)v [12288)part
    const int chunk = blockIdx.x;
    const int h     = blockIdx.y;
    const int n0    = chunk * CHUNK;
    const int tid   = threadIdx.x;

#pragma unroll
    for (int arr = 0; arr < 3; arr++) {
#pragma unroll
        for (int r = 0; r < 4; r++) {
            const int l = tid + r * 256;          // float4 idx 0..1023
            const int row = l >> 4, c = (l & 15) * 4;
            *(float4*)&hs[arr * 4096 + row * 64 + c] =
                *(const float4*)&g_qkv[(size_t)(n0 + row) * E3 + arr * 512 + h * 64 + c];
        }
    }
    __syncthreads();

    // qsum partial: thread (grp = tid>>6, d = tid&63) sums 16 tokens
    {
        const int d = tid & 63, grp = tid >> 6;
        float qa = 0.0f;
#pragma unroll
        for (int nn = 0; nn < 16; nn++)
            qa += hs[(grp * 16 + nn) * 64 + d];
        hs[12288 + grp * 64 + d] = qa;
    }

    // K^T V outer product: thread tile 4 d1 x 4 d2
    const int d1b = (tid >> 4) << 2;
    const int d2b = (tid & 15) << 2;
    float acc[4][4];
#pragma unroll
    for (int i = 0; i < 4; i++)
#pragma unroll
        for (int j = 0; j < 4; j++) acc[i][j] = 0.0f;

#pragma unroll 4
    for (int n = 0; n < 64; n++) {
        const float4 kv = *(const float4*)&hs[4096 + n * 64 + d1b];
        const float4 vv = *(const float4*)&hs[8192 + n * 64 + d2b];
        acc[0][0] = fmaf(kv.x, vv.x, acc[0][0]);
        acc[0][1] = fmaf(kv.x, vv.y, acc[0][1]);
        acc[0][2] = fmaf(kv.x, vv.z, acc[0][2]);
        acc[0][3] = fmaf(kv.x, vv.w, acc[0][3]);
        acc[1][0] = fmaf(kv.y, vv.x, acc[1][0]);
        acc[1][1] = fmaf(kv.y, vv.y, acc[1][1]);
        acc[1][2] = fmaf(kv.y, vv.z, acc[1][2]);
        acc[1][3] = fmaf(kv.y, vv.w, acc[1][3]);
        acc[2][0] = fmaf(kv.z, vv.x, acc[2][0]);
        acc[2][1] = fmaf(kv.z, vv.y, acc[2][1]);
        acc[2][2] = fmaf(kv.z, vv.z, acc[2][2]);
        acc[2][3] = fmaf(kv.z, vv.w, acc[2][3]);
        acc[3][0] = fmaf(kv.w, vv.x, acc[3][0]);
        acc[3][1] = fmaf(kv.w, vv.y, acc[3][1]);
        acc[3][2] = fmaf(kv.w, vv.z, acc[3][2]);
        acc[3][3] = fmaf(kv.w, vv.w, acc[3][3]);
    }

#pragma unroll
    for (int i = 0; i < 4; i++) {
        float4 o = { acc[i][0], acc[i][1], acc[i][2], acc[i][3] };
        *(float4*)&g_Mpart[((chunk * 8 + h) * 64 + d1b + i) * 64 + d2b] = o;
    }

    __syncthreads();
    if (tid < 64) {
        float s = hs[12288 + tid] + hs[12288 + 64 + tid]
                + hs[12288 + 128 + tid] + hs[12288 + 192 + tid];
        g_qsumpart[chunk * 512 + h * 64 + tid] = s;
    }
}

__global__ __launch_bounds__(256)
void reduce_parts_kernel()
{
    if (blockIdx.x < 128) {
        const int idx = blockIdx.x * 256 + threadIdx.x;
        float sum = 0.0f;
#pragma unroll
        for (int c = 0; c < NCHUNK; c++) sum += g_Mpart[c * 32768 + idx];
        g_M[idx] = sum;
    } else {
        for (int t = threadIdx.x; t < 512; t += 256) {
            float sum = 0.0f;
#pragma unroll
            for (int c = 0; c < NCHUNK; c++) sum += g_qsumpart[c * 512 + t];
            g_qsum[t] = sum;
        }
    }
}

// ---------------------------------------------------------------------------
// output: register-blocked (8n x 4d2 per thread). grid (32, 8), 256 threads.
// ---------------------------------------------------------------------------
__global__ __launch_bounds__(256)
void output_kernel(float* __restrict__ out)
{
    extern __shared__ float osm[];
    float (*Ms)[64] = (float(*)[64])osm;            // 64 x 64
    float (*qs)[64] = (float(*)[64])(osm + 4096);   // 128 x 64

    const int n0 = blockIdx.x * 128;
    const int h  = blockIdx.y;
    const int t  = threadIdx.x;

#pragma unroll
    for (int r = 0; r < 4; r++) {
        const int l = t + r * 256;
        *(float4*)&Ms[l >> 4][(l & 15) * 4] =
            *(const float4*)&g_M[h * 4096 + (l >> 4) * 64 + (l & 15) * 4];
    }
#pragma unroll
    for (int r = 0; r < 8; r++) {
        const int l = t + r * 256;
        *(float4*)&qs[l >> 4][(l & 15) * 4] =
            *(const float4*)&g_qkv[(size_t)(n0 + (l >> 4)) * E3 + h * 64 + (l & 15) * 4];
    }
    __syncthreads();

    const int tx = t & 15;
    const int ty = t >> 4;

    float acc[8][4];
#pragma unroll
    for (int i = 0; i < 8; i++)
#pragma unroll
        for (int j = 0; j < 4; j++) acc[i][j] = 0.0f;

#pragma unroll
    for (int d1 = 0; d1 < 64; d1++) {
        const float4 m4 = *(const float4*)&Ms[d1][tx * 4];
#pragma unroll
        for (int i = 0; i < 8; i++) {
            const float qv = qs[ty * 8 + i][d1];
            acc[i][0] = fmaf(qv, m4.x, acc[i][0]);
            acc[i][1] = fmaf(qv, m4.y, acc[i][1]);
            acc[i][2] = fmaf(qv, m4.z, acc[i][2]);
            acc[i][3] = fmaf(qv, m4.w, acc[i][3]);
        }
    }

#pragma unroll
    for (int i = 0; i < 8; i++) {
        const int n = n0 + ty * 8 + i;
        float4 o = { acc[i][0] * 0.125f, acc[i][1] * 0.125f,
                     acc[i][2] * 0.125f, acc[i][3] * 0.125f };
        *(float4*)&out[32768 + (size_t)((h << 12) + n) * 64 + tx * 4] = o;
    }
}

// ---------------------------------------------------------------------------
// coarse[h,n] = scale * qsum_h . k_h[n]
// ---------------------------------------------------------------------------
__global__ __launch_bounds__(256)
void coarse_kernel(float* __restrict__ out)
{
    __shared__ float qs[512];
    for (int l = threadIdx.x; l < 512; l += 256) qs[l] = g_qsum[l];
    __syncthreads();

    const int gid = blockIdx.x * 256 + threadIdx.x;
    const int h = gid >> 12, n = gid & 4095;
    const float4* kp = (const float4*)&g_qkv[(size_t)n * E3 + 512 + h * 64];
    const float4* qp = (const float4*)&qs[h * 64];
    float c = 0.0f;
#pragma unroll
    for (int i = 0; i < 16; i++) {
        const float4 k4 = kp[i], q4 = qp[i];
        c = fmaf(q4.x, k4.x, c); c = fmaf(q4.y, k4.y, c);
        c = fmaf(q4.z, k4.z, c); c = fmaf(q4.w, k4.w, c);
    }
    out[gid] = c * 0.125f;
}

// ---------------------------------------------------------------------------
extern "C" void kernel_launch(void* const* d_in, const int* in_sizes, int n_in,
                              void* d_out, int out_size)
{
    const float* x  = (const float*)d_in[0];   // [512, 4096]
    const float* Wq = (const float*)d_in[1];   // [512, 1536]
    const float* bq = (const float*)d_in[2];   // [1536]
    float* out = (float*)d_out;
    (void)in_sizes; (void)n_in; (void)out_size;

    cudaFuncSetAttribute(qkv_tf32_gemm, cudaFuncAttributeMaxDynamicSharedMemorySize, GEMM_SMEM);
    cudaFuncSetAttribute(output_kernel, cudaFuncAttributeMaxDynamicSharedMemorySize, 49152);
    cudaFuncSetAttribute(head_reduce_kernel, cudaFuncAttributeMaxDynamicSharedMemorySize, HR_SMEM);

    qkv_tf32_gemm<<<dim3(12, 32), 256, GEMM_SMEM>>>(x, Wq, bq);

    head_reduce_kernel<<<dim3(NCHUNK, 8), 256, HR_SMEM>>>();
    reduce_parts_kernel<<<129, 256>>>();

    output_kernel<<<dim3(32, 8), 256, 49152>>>(out);
    coarse_kernel<<<128, 256>>>(out);
}

// round 11
// speedup vs baseline: 3.0836x; 1.1020x over previous
#include <cuda_runtime.h>
#include <cstdint>

// MHSA without softmax, 3 kernels:
//  K1 fused_gemm: qkv = Xs@W + b via TF32 mma.sync.
//     - Q-CTAs (bx<4): write q[4096][512], + column-sum partials (qsumpart)
//     - KV-CTAs (bx>=4, head h): compute [k_h | v_h] tile, write k, and
//       reduce Mpart[rowblk,h] = K_tile^T V_tile in-block (v never hits DRAM)
//  K2 reduce_parts: g_M = sum Mpart, g_qsum = sum qsumpart  (fixed order)
//  K3 output_coarse: out = scale * q @ M_h ; coarse = scale * qsum_h . k_h[n]
// d_out: [coarse 8*4096][output 8*4096*64]

#define NTOK 4096
#define E3   1536
#define NRB  32                 // 32 row-blocks of 128 tokens

__device__ float g_q[NTOK * 512];
__device__ float g_k[NTOK * 512];
__device__ float g_Mpart[NRB * 8 * 64 * 64];
__device__ float g_qsumpart[NRB * 512];
__device__ float g_M[8 * 64 * 64];
__device__ float g_qsum[512];

// ---------------------------------------------------------------------------
__device__ __forceinline__ uint32_t smem_u32(const void* p) {
    uint32_t a;
    asm("{ .reg .u64 t; cvta.to.shared.u64 t, %1; cvt.u32.u64 %0, t; }" : "=r"(a) : "l"(p));
    return a;
}
#define CP_ASYNC16(sa, gp) \
    asm volatile("cp.async.cg.shared.global [%0], [%1], 16;" :: "r"(sa), "l"(gp))
#define CP_COMMIT() asm volatile("cp.async.commit_group;")
#define CP_WAIT1()  asm volatile("cp.async.wait_group 1;")
#define CP_WAIT0()  asm volatile("cp.async.wait_group 0;")

__device__ __forceinline__ uint32_t f2tf32(float f) {
    uint32_t r;
    asm("cvt.rna.tf32.f32 %0, %1;" : "=r"(r) : "f"(f));
    return r;
}
#define MMA_TF32(d, a, b0, b1) \
    asm volatile("mma.sync.aligned.m16n8k8.row.col.f32.tf32.tf32.f32 " \
        "{%0,%1,%2,%3},{%4,%5,%6,%7},{%8,%9},{%0,%1,%2,%3};" \
        : "+f"((d)[0]), "+f"((d)[1]), "+f"((d)[2]), "+f"((d)[3]) \
        : "r"((a)[0]), "r"((a)[1]), "r"((a)[2]), "r"((a)[3]), "r"(b0), "r"(b1))

// ---------------------------------------------------------------------------
// K1: fused TF32 GEMM + per-tile reductions.
// CTA 128x128, 8 warps (2Mx4N, warp 64x32), BK=32, 3-stage cp.async,
// ONE __syncthreads per K-iteration. smem stride 136 floats (conflict-free
// fragment LDS: bank = 8*kb + er, all 32 distinct).
// ---------------------------------------------------------------------------
#define SST         136
#define STAGE_FLT   (2 * 32 * SST)              // A then B: 8704 floats
#define STAGE_BYT   (STAGE_FLT * 4)             // 34816 B
#define GEMM_SMEM   (3 * STAGE_BYT)             // 104448 B

__global__ __launch_bounds__(256)
void fused_gemm(const float* __restrict__ X,
                const float* __restrict__ W,
                const float* __restrict__ bias)
{
    extern __shared__ float sm[];
    const uint32_t smb = smem_u32(sm);
    const int tid = threadIdx.x;
    const int lane = tid & 31, wid = tid >> 5;
    const int bx = blockIdx.x;               // 0..11
    const int by = blockIdx.y;               // 0..31
    const int bm = by * 128;
    const bool isQ = (bx < 4);
    const int bn = isQ ? bx * 128 : 0;       // q col base
    const int hh = bx - 4;                   // head for kv-CTAs
    const int wm = (wid & 1) * 64, wn = (wid >> 1) * 32;

    float acc[4][4][4];
#pragma unroll
    for (int i = 0; i < 4; i++)
#pragma unroll
        for (int j = 0; j < 4; j++)
#pragma unroll
            for (int r = 0; r < 4; r++) acc[i][j][r] = 0.0f;

    auto ldstage = [&](int it, int s) {
        const int k0 = it * 32;
        const uint32_t sa = smb + s * STAGE_BYT;
#pragma unroll
        for (int i = 0; i < 4; i++) {
            const int idx = i * 256 + tid;
            const int row = idx >> 5;             // 0..31
            const int c   = (idx & 31) * 4;       // 0..124
            CP_ASYNC16(sa + (uint32_t)(row * SST + c) * 4,
                       X + (size_t)(k0 + row) * NTOK + bm + c);
        }
#pragma unroll
        for (int i = 0; i < 4; i++) {
            const int idx = i * 256 + tid;
            const int row = idx >> 5;
            const int c   = (idx & 31) * 4;
            const int gc  = isQ ? (bn + c)
                                : (c < 64 ? 512 + 64 * hh + c : 960 + 64 * hh + c);
            CP_ASYNC16(sa + (uint32_t)(32 * SST + row * SST + c) * 4,
                       W + (size_t)(k0 + row) * E3 + gc);
        }
        CP_COMMIT();
    };

    ldstage(0, 0);
    ldstage(1, 1);

    for (int it = 0; it < 16; ++it) {
        if (it >= 15) { CP_WAIT0(); } else { CP_WAIT1(); }
        __syncthreads();                               // all done with it-1
        if (it + 2 < 16) ldstage(it + 2, (it + 2) % 3);  // stage (it-1)%3, now free

        const float* As = sm + (it % 3) * STAGE_FLT;
        const float* Bs = As + 32 * SST;

#pragma unroll
        for (int kk = 0; kk < 4; kk++) {
            const int kb = kk * 8 + (lane & 3);
            uint32_t a[4][4], b[4][2];
#pragma unroll
            for (int mt = 0; mt < 4; mt++) {
                const int m = wm + mt * 16 + (lane >> 2);
                a[mt][0] = f2tf32(As[kb * SST + m]);
                a[mt][1] = f2tf32(As[kb * SST + m + 8]);
                a[mt][2] = f2tf32(As[(kb + 4) * SST + m]);
                a[mt][3] = f2tf32(As[(kb + 4) * SST + m + 8]);
            }
#pragma unroll
            for (int n8 = 0; n8 < 4; n8++) {
                const int n = wn + n8 * 8 + (lane >> 2);
                b[n8][0] = f2tf32(Bs[kb * SST + n]);
                b[n8][1] = f2tf32(Bs[(kb + 4) * SST + n]);
            }
#pragma unroll
            for (int mt = 0; mt < 4; mt++)
#pragma unroll
                for (int n8 = 0; n8 < 4; n8++)
                    MMA_TF32(acc[mt][n8], a[mt], b[n8][0], b[n8][1]);
        }
        // no trailing barrier: next iteration's barrier provides it
    }
    __syncthreads();   // mainloop smem now reusable

    const int er = lane >> 2, ec = (lane & 3) * 2;

    if (isQ) {
        // ---- write q (+bias) ----
#pragma unroll
        for (int n8 = 0; n8 < 4; n8++) {
            const int c = wn + n8 * 8 + ec;
            const float2 bv = *(const float2*)&bias[bn + c];
#pragma unroll
            for (int mt = 0; mt < 4; mt++) {
                const int r = bm + wm + mt * 16 + er;
                float2 o0 = { acc[mt][n8][0] + bv.x, acc[mt][n8][1] + bv.y };
                *(float2*)&g_q[(size_t)r * 512 + bn + c] = o0;
                float2 o1 = { acc[mt][n8][2] + bv.x, acc[mt][n8][3] + bv.y };
                *(float2*)&g_q[(size_t)(r + 8) * 512 + bn + c] = o1;
            }
        }
        // ---- column partial sums (qsum over this 128-token block) ----
        float s0[4], s1[4];
#pragma unroll
        for (int n8 = 0; n8 < 4; n8++) {
            s0[n8] = 0.0f; s1[n8] = 0.0f;
#pragma unroll
            for (int mt = 0; mt < 4; mt++) {
                s0[n8] += acc[mt][n8][0] + acc[mt][n8][2];
                s1[n8] += acc[mt][n8][1] + acc[mt][n8][3];
            }
#pragma unroll
            for (int msk = 16; msk >= 4; msk >>= 1) {
                s0[n8] += __shfl_xor_sync(0xffffffff, s0[n8], msk);
                s1[n8] += __shfl_xor_sync(0xffffffff, s1[n8], msk);
            }
        }
        float* qsp = sm;                 // [2][128]
        if (lane < 4) {
#pragma unroll
            for (int n8 = 0; n8 < 4; n8++) {
                const int c = wn + n8 * 8 + lane * 2;
                qsp[(wid & 1) * 128 + c]     = s0[n8];
                qsp[(wid & 1) * 128 + c + 1] = s1[n8];
            }
        }
        __syncthreads();
        if (tid < 128)
            g_qsumpart[by * 512 + bn + tid] =
                qsp[tid] + qsp[128 + tid] + 128.0f * bias[bn + tid];
    } else {
        // ---- stage C (+bias) into smem: Cs[128][136], cols [k_h | v_h] ----
        float* Cs = sm;
#pragma unroll
        for (int n8 = 0; n8 < 4; n8++) {
            const int c = wn + n8 * 8 + ec;
            const int gc = (c < 64) ? 512 + 64 * hh + c : 960 + 64 * hh + c;
            const float2 bv = *(const float2*)&bias[gc];
#pragma unroll
            for (int mt = 0; mt < 4; mt++) {
                const int r = wm + mt * 16 + er;
                Cs[r * SST + c]           = acc[mt][n8][0] + bv.x;
                Cs[r * SST + c + 1]       = acc[mt][n8][1] + bv.y;
                Cs[(r + 8) * SST + c]     = acc[mt][n8][2] + bv.x;
                Cs[(r + 8) * SST + c + 1] = acc[mt][n8][3] + bv.y;
            }
        }
        __syncthreads();
        // ---- write k half to g_k ----
#pragma unroll
        for (int i = 0; i < 8; i++) {
            const int idx = i * 256 + tid;        // 2048 float4s
            const int row = idx >> 4, c = (idx & 15) * 4;
            *(float4*)&g_k[(size_t)(bm + row) * 512 + hh * 64 + c] =
                *(const float4*)&Cs[row * SST + c];
        }
        // ---- Mpart = K_tile^T V_tile over 128 tokens; thread tile 4x4 ----
        const int d1b = (tid >> 4) << 2;
        const int d2b = (tid & 15) << 2;
        float m2[4][4];
#pragma unroll
        for (int i = 0; i < 4; i++)
#pragma unroll
            for (int j = 0; j < 4; j++) m2[i][j] = 0.0f;

#pragma unroll 4
        for (int n = 0; n < 128; n++) {
            const float4 kv = *(const float4*)&Cs[n * SST + d1b];
            const float4 vv = *(const float4*)&Cs[n * SST + 64 + d2b];
            m2[0][0] = fmaf(kv.x, vv.x, m2[0][0]);
            m2[0][1] = fmaf(kv.x, vv.y, m2[0][1]);
            m2[0][2] = fmaf(kv.x, vv.z, m2[0][2]);
            m2[0][3] = fmaf(kv.x, vv.w, m2[0][3]);
            m2[1][0] = fmaf(kv.y, vv.x, m2[1][0]);
            m2[1][1] = fmaf(kv.y, vv.y, m2[1][1]);
            m2[1][2] = fmaf(kv.y, vv.z, m2[1][2]);
            m2[1][3] = fmaf(kv.y, vv.w, m2[1][3]);
            m2[2][0] = fmaf(kv.z, vv.x, m2[2][0]);
            m2[2][1] = fmaf(kv.z, vv.y, m2[2][1]);
            m2[2][2] = fmaf(kv.z, vv.z, m2[2][2]);
            m2[2][3] = fmaf(kv.z, vv.w, m2[2][3]);
            m2[3][0] = fmaf(kv.w, vv.x, m2[3][0]);
            m2[3][1] = fmaf(kv.w, vv.y, m2[3][1]);
            m2[3][2] = fmaf(kv.w, vv.z, m2[3][2]);
            m2[3][3] = fmaf(kv.w, vv.w, m2[3][3]);
        }
#pragma unroll
        for (int i = 0; i < 4; i++) {
            float4 o = { m2[i][0], m2[i][1], m2[i][2], m2[i][3] };
            *(float4*)&g_Mpart[((by * 8 + hh) * 64 + d1b + i) * 64 + d2b] = o;
        }
    }
}

// ---------------------------------------------------------------------------
// K2: deterministic final reductions.
// ---------------------------------------------------------------------------
__global__ __launch_bounds__(256)
void reduce_parts_kernel()
{
    if (blockIdx.x < 128) {
        const int idx = blockIdx.x * 256 + threadIdx.x;   // 0..32767
        float sum = 0.0f;
#pragma unroll
        for (int c = 0; c < NRB; c++) sum += g_Mpart[c * 32768 + idx];
        g_M[idx] = sum;
    } else {
        for (int t = threadIdx.x; t < 512; t += 256) {
            float sum = 0.0f;
#pragma unroll
            for (int c = 0; c < NRB; c++) sum += g_qsumpart[c * 512 + t];
            g_qsum[t] = sum;
        }
    }
}

// ---------------------------------------------------------------------------
// K3: output + coarse. grid (32, 8), 256 threads.
//   out[h,n,d2]  = scale * sum_d1 q_h[n,d1] * M_h[d1,d2]
//   coarse[h,n]  = scale * dot(qsum_h, k_h[n])
// ---------------------------------------------------------------------------
#define OUT_SMEM ((4096 + 8192 + 64) * 4)

__global__ __launch_bounds__(256)
void output_coarse_kernel(float* __restrict__ out)
{
    extern __shared__ float osm[];
    float (*Ms)[64] = (float(*)[64])osm;             // 64 x 64
    float (*qs)[64] = (float(*)[64])(osm + 4096);    // 128 x 64
    float* qsh = osm + 12288;                        // 64

    const int n0 = blockIdx.x * 128;
    const int h  = blockIdx.y;
    const int t  = threadIdx.x;

#pragma unroll
    for (int r = 0; r < 4; r++) {
        const int l = t + r * 256;
        *(float4*)&Ms[l >> 4][(l & 15) * 4] =
            *(const float4*)&g_M[h * 4096 + (l >> 4) * 64 + (l & 15) * 4];
    }
#pragma unroll
    for (int r = 0; r < 8; r++) {
        const int l = t + r * 256;
        *(float4*)&qs[l >> 4][(l & 15) * 4] =
            *(const float4*)&g_q[(size_t)(n0 + (l >> 4)) * 512 + h * 64 + (l & 15) * 4];
    }
    if (t < 64) qsh[t] = g_qsum[h * 64 + t];
    __syncthreads();

    const int tx = t & 15;
    const int ty = t >> 4;

    float acc[8][4];
#pragma unroll
    for (int i = 0; i < 8; i++)
#pragma unroll
        for (int j = 0; j < 4; j++) acc[i][j] = 0.0f;

#pragma unroll
    for (int d1 = 0; d1 < 64; d1++) {
        const float4 m4 = *(const float4*)&Ms[d1][tx * 4];
#pragma unroll
        for (int i = 0; i < 8; i++) {
            const float qv = qs[ty * 8 + i][d1];
            acc[i][0] = fmaf(qv, m4.x, acc[i][0]);
            acc[i][1] = fmaf(qv, m4.y, acc[i][1]);
            acc[i][2] = fmaf(qv, m4.z, acc[i][2]);
            acc[i][3] = fmaf(qv, m4.w, acc[i][3]);
        }
    }

#pragma unroll
    for (int i = 0; i < 8; i++) {
        const int n = n0 + ty * 8 + i;
        float4 o = { acc[i][0] * 0.125f, acc[i][1] * 0.125f,
                     acc[i][2] * 0.125f, acc[i][3] * 0.125f };
        *(float4*)&out[32768 + (size_t)((h << 12) + n) * 64 + tx * 4] = o;
    }

    // coarse: one n per thread (tid < 128)
    if (t < 128) {
        const int n = n0 + t;
        const float4* kp = (const float4*)&g_k[(size_t)n * 512 + h * 64];
        float c = 0.0f;
#pragma unroll
        for (int i = 0; i < 16; i++) {
            const float4 k4 = kp[i];
            const float4 q4 = *(const float4*)&qsh[i * 4];
            c = fmaf(q4.x, k4.x, c); c = fmaf(q4.y, k4.y, c);
            c = fmaf(q4.z, k4.z, c); c = fmaf(q4.w, k4.w, c);
        }
        out[(h << 12) + n] = c * 0.125f;
    }
}

// ---------------------------------------------------------------------------
extern "C" void kernel_launch(void* const* d_in, const int* in_sizes, int n_in,
                              void* d_out, int out_size)
{
    const float* x  = (const float*)d_in[0];   // [512, 4096]
    const float* Wq = (const float*)d_in[1];   // [512, 1536]
    const float* bq = (const float*)d_in[2];   // [1536]
    float* out = (float*)d_out;
    (void)in_sizes; (void)n_in; (void)out_size;

    cudaFuncSetAttribute(fused_gemm, cudaFuncAttributeMaxDynamicSharedMemorySize, GEMM_SMEM);
    cudaFuncSetAttribute(output_coarse_kernel, cudaFuncAttributeMaxDynamicSharedMemorySize, OUT_SMEM);

    fused_gemm<<<dim3(12, 32), 256, GEMM_SMEM>>>(x, Wq, bq);
    reduce_parts_kernel<<<129, 256>>>();
    output_coarse_kernel<<<dim3(32, 8), 256, OUT_SMEM>>>(out);
}